// round 4
// baseline (speedup 1.0000x reference)
#include <cuda_runtime.h>

typedef unsigned long long ull;

// ---------------- device scratch (no allocations allowed) ----------------
__device__ float g_gatesA[(size_t)512 * 128 * 4096]; // t in [0,512)   : [t][b][4H]
__device__ float g_gatesB[(size_t)512 * 128 * 4096]; // t in [512,1024)
__device__ float g_y0[(size_t)1024 * 128 * 1024];    // [t][b][h]
__device__ float g_y1[(size_t)1024 * 128 * 1024];
__device__ float g_wt[4 * 1024 * 1024];              // packed Whh: [k][g][j]
__device__ float g_ht[2][1024 * 128];                // transposed h: [k][b]
__device__ float g_hT[128 * 1024];                   // final hidden, [b][h]
__device__ float g_z1[128 * 512];
__device__ float g_z2[128 * 256];

__device__ unsigned g_bar_cnt = 0;
__device__ volatile unsigned g_bar_gen = 0;

// ---------------- helpers ----------------
__device__ __forceinline__ ull pk(float a, float b) {
    ull r; asm("mov.b64 %0,{%1,%2};" : "=l"(r) : "f"(a), "f"(b)); return r;
}
__device__ __forceinline__ void unpk(ull v, float& a, float& b) {
    asm("mov.b64 {%0,%1},%2;" : "=f"(a), "=f"(b) : "l"(v));
}
__device__ __forceinline__ ull f2fma(ull a, ull b, ull c) {
    ull d; asm("fma.rn.f32x2 %0,%1,%2,%3;" : "=l"(d) : "l"(a), "l"(b), "l"(c)); return d;
}
__device__ __forceinline__ float sigm(float x) {
    return __fdividef(1.f, 1.f + __expf(-x));
}
__device__ __forceinline__ float tanh_(float x) {
    return 1.f - __fdividef(2.f, 1.f + __expf(2.f * x));
}

// grid-wide barrier: all 128 blocks co-resident (grid must be 128)
__device__ __forceinline__ void grid_bar() {
    __syncthreads();
    if (threadIdx.x == 0) {
        __threadfence();
        unsigned g = g_bar_gen;
        unsigned a = atomicAdd(&g_bar_cnt, 1u);
        if (a == 127u) {
            g_bar_cnt = 0u;
            __threadfence();
            g_bar_gen = g + 1u;
        } else {
            while (g_bar_gen == g) { __nanosleep(64); }
        }
    }
    __syncthreads();
}

// ---------------- pack Whh[4H,H] -> g_wt[k][g][j] ----------------
__global__ void pack_whh(const float* __restrict__ Whh) {
    int idx = blockIdx.x * blockDim.x + threadIdx.x; // 4M
    int j = idx & 1023, g = (idx >> 10) & 3, k = idx >> 12;
    g_wt[idx] = Whh[((size_t)((g << 10) | j)) * 1024 + k];
}

// ---------------- generic C = A @ W^T + b0 (+b1), tiled 64x64x16, f32x2 ----------------
// asel: 0 = Aext layer0 x mapping ([B,T,IN], row m = t*B+b)
//       1 = g_y0, 2 = g_y1, 3 = g_hT, 4 = g_z1   (row-major, lda=K)
// csel: 0 = gates (split halves, ldc=4096), 1 = g_z1 (ldc=512), 2 = g_z2 (ldc=256)
__global__ __launch_bounds__(256) void gemm_tn(
    const float* __restrict__ Aext, const float* __restrict__ W,
    const float* __restrict__ b0, const float* __restrict__ b1,
    int K, int asel, int csel)
{
    __shared__ float As[16][68];
    __shared__ float Bs[16][68];
    const int tid = threadIdx.x;
    const int tx = tid & 15, ty = tid >> 4;
    const int m0 = blockIdx.y * 64, n0 = blockIdx.x * 64;

    const float* base = Aext;
    if (asel == 1) base = g_y0;
    else if (asel == 2) base = g_y1;
    else if (asel == 3) base = g_hT;
    else if (asel == 4) base = g_z1;

    const int r = tid >> 2, kq = tid & 3;
    const float* arow;
    if (asel == 0) {
        int mg = m0 + r;
        arow = Aext + ((size_t)(mg & 127) * 1024 + (size_t)(mg >> 7)) * 128;
    } else {
        arow = base + (size_t)(m0 + r) * K;
    }
    const float* wrow = W + (size_t)(n0 + r) * K;

    ull acc[4][2];
#pragma unroll
    for (int i = 0; i < 4; i++) { acc[i][0] = 0ull; acc[i][1] = 0ull; }

    const int nkt = K >> 4;
    float4 av = *(const float4*)(arow + kq * 4);
    float4 wv = *(const float4*)(wrow + kq * 4);

    for (int kt = 0; kt < nkt; kt++) {
        As[kq * 4 + 0][r] = av.x; As[kq * 4 + 1][r] = av.y;
        As[kq * 4 + 2][r] = av.z; As[kq * 4 + 3][r] = av.w;
        Bs[kq * 4 + 0][r] = wv.x; Bs[kq * 4 + 1][r] = wv.y;
        Bs[kq * 4 + 2][r] = wv.z; Bs[kq * 4 + 3][r] = wv.w;
        __syncthreads();
        if (kt + 1 < nkt) {
            av = *(const float4*)(arow + (kt + 1) * 16 + kq * 4);
            wv = *(const float4*)(wrow + (kt + 1) * 16 + kq * 4);
        }
#pragma unroll
        for (int k = 0; k < 16; k++) {
            float4 a4 = *(const float4*)&As[k][ty * 4];
            float4 b4 = *(const float4*)&Bs[k][tx * 4];
            ull bb01 = pk(b4.x, b4.y), bb23 = pk(b4.z, b4.w);
            ull ad;
            ad = pk(a4.x, a4.x); acc[0][0] = f2fma(ad, bb01, acc[0][0]); acc[0][1] = f2fma(ad, bb23, acc[0][1]);
            ad = pk(a4.y, a4.y); acc[1][0] = f2fma(ad, bb01, acc[1][0]); acc[1][1] = f2fma(ad, bb23, acc[1][1]);
            ad = pk(a4.z, a4.z); acc[2][0] = f2fma(ad, bb01, acc[2][0]); acc[2][1] = f2fma(ad, bb23, acc[2][1]);
            ad = pk(a4.w, a4.w); acc[3][0] = f2fma(ad, bb01, acc[3][0]); acc[3][1] = f2fma(ad, bb23, acc[3][1]);
        }
        __syncthreads();
    }

    const int n = n0 + tx * 4;
    float bb[4];
#pragma unroll
    for (int jj = 0; jj < 4; jj++) {
        bb[jj] = b0[n + jj];
        if (b1) bb[jj] += b1[n + jj];
    }
#pragma unroll
    for (int mi = 0; mi < 4; mi++) {
        int m = m0 + ty * 4 + mi;
        float c0, c1, c2, c3;
        unpk(acc[mi][0], c0, c1);
        unpk(acc[mi][1], c2, c3);
        float4 outv = make_float4(c0 + bb[0], c1 + bb[1], c2 + bb[2], c3 + bb[3]);
        float* crow;
        if (csel == 0)      crow = (m < 65536 ? g_gatesA : g_gatesB) + (size_t)(m & 65535) * 4096;
        else if (csel == 1) crow = g_z1 + (size_t)m * 512;
        else                crow = g_z2 + (size_t)m * 256;
        *(float4*)(crow + n) = outv;
    }
}

// ---------------- persistent LSTM layer: 1024 steps in one kernel -------------
// grid = 128 blocks (j-tile of 8), 256 threads.
// Thread = (j = tid&7, bg = tid>>3): 4 b x 1 j x 4 gates, f32x2 packed over b.
// ysel: 0 -> write g_y0, 1 -> write g_y1, 2 -> no y, write g_hT at t==1023.
__global__ __launch_bounds__(256) void lstm_layer(int ysel)
{
    __shared__ float h_s[2][32 * 128];  // [buf][k][b]
    __shared__ float w_s[2][32 * 64];   // [buf][k][g][j*2] duplicated pairs
    const int tid = threadIdx.x;
    const int j = tid & 7, bg = tid >> 3;
    const int j0 = blockIdx.x << 3;
    const int jg = j0 + j;
    const int b0 = bg << 2;

    float cc[4] = {0.f, 0.f, 0.f, 0.f};

    for (int t = 0; t < 1024; t++) {
        const float* __restrict__ gp =
            (t < 512 ? g_gatesA : g_gatesB) + (size_t)(t & 511) * (128 * 4096);

        // prefetch gate pre-activations (streaming; latency hidden by k-loop)
        float ga[4][4];
#pragma unroll
        for (int i = 0; i < 4; i++) {
            const float* gb = gp + (size_t)(b0 + i) * 4096 + jg;
            ga[i][0] = __ldcs(gb);
            ga[i][1] = __ldcs(gb + 1024);
            ga[i][2] = __ldcs(gb + 2048);
            ga[i][3] = __ldcs(gb + 3072);
        }

        float ad[4][4]; // recurrent contribution [b_i][gate]
        if (t > 0) {
            const float* __restrict__ h_in = g_ht[t & 1];
            ull acc[2][4];
#pragma unroll
            for (int p = 0; p < 2; p++)
#pragma unroll
                for (int g = 0; g < 4; g++) acc[p][g] = 0ull;

            // prefetch tile 0
            float4 hp[4]; float2 wp[2];
#pragma unroll
            for (int r = 0; r < 4; r++) {
                int s = tid + 256 * r; int kk = s >> 5, bc = s & 31;
                hp[r] = __ldcg((const float4*)(h_in + kk * 128 + bc * 4));
            }
#pragma unroll
            for (int r = 0; r < 2; r++) {
                int s = tid + 256 * r; int kk = s >> 4, g = (s >> 2) & 3, jp = s & 3;
                wp[r] = *(const float2*)(g_wt + ((size_t)(kk * 4 + g)) * 1024 + j0 + jp * 2);
            }

            for (int kt = 0; kt < 32; kt++) {
                const int buf = kt & 1;
                // store current tile
#pragma unroll
                for (int r = 0; r < 4; r++) {
                    int s = tid + 256 * r; int kk = s >> 5, bc = s & 31;
                    *(float4*)&h_s[buf][kk * 128 + bc * 4] = hp[r];
                }
#pragma unroll
                for (int r = 0; r < 2; r++) {
                    int s = tid + 256 * r; int kk = s >> 4, g = (s >> 2) & 3, jp = s & 3;
                    float2 d0 = make_float2(wp[r].x, wp[r].x);
                    float2 d1 = make_float2(wp[r].y, wp[r].y);
                    *(float2*)&w_s[buf][kk * 64 + g * 16 + jp * 4]     = d0;
                    *(float2*)&w_s[buf][kk * 64 + g * 16 + jp * 4 + 2] = d1;
                }
                __syncthreads();
                // prefetch next tile
                if (kt + 1 < 32) {
                    const int k0 = (kt + 1) * 32;
#pragma unroll
                    for (int r = 0; r < 4; r++) {
                        int s = tid + 256 * r; int kk = s >> 5, bc = s & 31;
                        hp[r] = __ldcg((const float4*)(h_in + (k0 + kk) * 128 + bc * 4));
                    }
#pragma unroll
                    for (int r = 0; r < 2; r++) {
                        int s = tid + 256 * r; int kk = s >> 4, g = (s >> 2) & 3, jp = s & 3;
                        wp[r] = *(const float2*)(g_wt + ((size_t)((k0 + kk) * 4 + g)) * 1024 + j0 + jp * 2);
                    }
                }
                // compute 32 k
#pragma unroll
                for (int k = 0; k < 32; k++) {
                    ull h01 = *(const ull*)&h_s[buf][k * 128 + b0];
                    ull h23 = *(const ull*)&h_s[buf][k * 128 + b0 + 2];
#pragma unroll
                    for (int g = 0; g < 4; g++) {
                        ull wd = *(const ull*)&w_s[buf][k * 64 + g * 16 + j * 2];
                        acc[0][g] = f2fma(h01, wd, acc[0][g]);
                        acc[1][g] = f2fma(h23, wd, acc[1][g]);
                    }
                }
                __syncthreads();
            }
#pragma unroll
            for (int p = 0; p < 2; p++)
#pragma unroll
                for (int g = 0; g < 4; g++)
                    unpk(acc[p][g], ad[2 * p][g], ad[2 * p + 1][g]);
        } else {
#pragma unroll
            for (int i = 0; i < 4; i++)
#pragma unroll
                for (int g = 0; g < 4; g++) ad[i][g] = 0.f;
        }

        // epilogue: activations + state update (c lives in registers)
        float hv[4];
#pragma unroll
        for (int i = 0; i < 4; i++) {
            float xi = ga[i][0] + ad[i][0];
            float xf = ga[i][1] + ad[i][1];
            float xg = ga[i][2] + ad[i][2];
            float xo = ga[i][3] + ad[i][3];
            float ii = sigm(xi), ff = sigm(xf), gg = tanh_(xg), oo = sigm(xo);
            cc[i] = ff * cc[i] + ii * gg;
            hv[i] = oo * tanh_(cc[i]);
        }
        // h_out transposed [k=j][b]
        *(float4*)(g_ht[(t & 1) ^ 1] + (size_t)jg * 128 + b0) =
            make_float4(hv[0], hv[1], hv[2], hv[3]);
        if (ysel == 0) {
#pragma unroll
            for (int i = 0; i < 4; i++)
                g_y0[((size_t)t * 128 + b0 + i) * 1024 + jg] = hv[i];
        } else if (ysel == 1) {
#pragma unroll
            for (int i = 0; i < 4; i++)
                g_y1[((size_t)t * 128 + b0 + i) * 1024 + jg] = hv[i];
        } else if (t == 1023) {
#pragma unroll
            for (int i = 0; i < 4; i++)
                g_hT[(size_t)(b0 + i) * 1024 + jg] = hv[i];
        }

        grid_bar();
    }
}

// ---------------- BN (eval) + ReLU, in place on g_z1/g_z2 ----------------
__global__ void bn_relu(int sel, const float* __restrict__ gg, const float* __restrict__ bb,
                        const float* __restrict__ mm, const float* __restrict__ vv, int N)
{
    int idx = blockIdx.x * blockDim.x + threadIdx.x;
    if (idx < 128 * N) {
        int n = idx % N;
        float* Z = (sel == 1) ? g_z1 : g_z2;
        float x = Z[idx];
        x = (x - mm[n]) * rsqrtf(vv[n] + 1e-5f) * gg[n] + bb[n];
        Z[idx] = fmaxf(x, 0.f);
    }
}

// ---------------- final fc3 ----------------
__global__ void fc3_k(const float* __restrict__ W, const float* __restrict__ bias,
                      float* __restrict__ out)
{
    int n = blockIdx.x;     // 0..27
    int b = threadIdx.x;    // 0..127
    const float* z = g_z2 + b * 256;
    const float* w = W + n * 256;
    float acc = 0.f;
#pragma unroll 8
    for (int k = 0; k < 256; k += 4) {
        float4 zv = *(const float4*)(z + k);
        float4 wv = *(const float4*)(w + k);
        acc += zv.x * wv.x + zv.y * wv.y + zv.z * wv.z + zv.w * wv.w;
    }
    out[b * 28 + n] = acc + bias[n];
}

// ---------------- launch ----------------
extern "C" void kernel_launch(void* const* d_in, const int* in_sizes, int n_in,
                              void* d_out, int out_size)
{
    const float* x = (const float*)d_in[0];
    const float* Wih[3] = {(const float*)d_in[1], (const float*)d_in[5], (const float*)d_in[9]};
    const float* Whh[3] = {(const float*)d_in[2], (const float*)d_in[6], (const float*)d_in[10]};
    const float* bih[3] = {(const float*)d_in[3], (const float*)d_in[7], (const float*)d_in[11]};
    const float* bhh[3] = {(const float*)d_in[4], (const float*)d_in[8], (const float*)d_in[12]};
    const float* fc1_w = (const float*)d_in[13]; const float* fc1_b = (const float*)d_in[14];
    const float* bn1_g = (const float*)d_in[15]; const float* bn1_b = (const float*)d_in[16];
    const float* bn1_m = (const float*)d_in[17]; const float* bn1_v = (const float*)d_in[18];
    const float* fc2_w = (const float*)d_in[19]; const float* fc2_b = (const float*)d_in[20];
    const float* bn2_g = (const float*)d_in[21]; const float* bn2_b = (const float*)d_in[22];
    const float* bn2_m = (const float*)d_in[23]; const float* bn2_v = (const float*)d_in[24];
    const float* fc3_w = (const float*)d_in[25]; const float* fc3_b = (const float*)d_in[26];

    for (int l = 0; l < 3; l++) {
        pack_whh<<<16384, 256>>>(Whh[l]);
        int K = (l == 0) ? 128 : 1024;
        int asel = (l == 0) ? 0 : ((l == 1) ? 1 : 2);
        gemm_tn<<<dim3(64, 2048), 256>>>((l == 0) ? x : nullptr, Wih[l], bih[l], bhh[l],
                                         K, asel, 0);
        int ysel = (l == 0) ? 0 : ((l == 1) ? 1 : 2);
        lstm_layer<<<128, 256>>>(ysel);
    }

    // head: final hidden of layer 2 is in g_hT
    gemm_tn<<<dim3(8, 2), 256>>>(nullptr, fc1_w, fc1_b, nullptr, 1024, 3, 1);
    bn_relu<<<256, 256>>>(1, bn1_g, bn1_b, bn1_m, bn1_v, 512);
    gemm_tn<<<dim3(4, 2), 256>>>(nullptr, fc2_w, fc2_b, nullptr, 512, 4, 2);
    bn_relu<<<128, 256>>>(2, bn2_g, bn2_b, bn2_m, bn2_v, 256);
    fc3_k<<<28, 128>>>(fc3_w, fc3_b, (float*)d_out);
}

// round 6
// speedup vs baseline: 1.0641x; 1.0641x over previous
#include <cuda_runtime.h>

typedef unsigned long long ull;

// ---------------- device scratch (no allocations allowed) ----------------
__device__ float g_gatesA[(size_t)512 * 128 * 4096]; // t in [0,512)   : [t][b][4H]
__device__ float g_gatesB[(size_t)512 * 128 * 4096]; // t in [512,1024)
__device__ float g_y0[(size_t)1024 * 128 * 1024];    // [t][b][h]
__device__ float g_y1[(size_t)1024 * 128 * 1024];
__device__ float g_ht[2][1024 * 128];                // transposed h: [k][b]
__device__ float g_hT[128 * 1024];                   // final hidden, [b][h]
__device__ float g_z1[128 * 512];
__device__ float g_z2[128 * 256];

__device__ unsigned g_bar_cnt = 0;
__device__ volatile unsigned g_bar_gen = 0;

// ---------------- helpers ----------------
__device__ __forceinline__ ull pk(float a, float b) {
    ull r; asm("mov.b64 %0,{%1,%2};" : "=l"(r) : "f"(a), "f"(b)); return r;
}
__device__ __forceinline__ void unpk(ull v, float& a, float& b) {
    asm("mov.b64 {%0,%1},%2;" : "=f"(a), "=f"(b) : "l"(v));
}
__device__ __forceinline__ ull f2fma(ull a, ull b, ull c) {
    ull d; asm("fma.rn.f32x2 %0,%1,%2,%3;" : "=l"(d) : "l"(a), "l"(b), "l"(c)); return d;
}
__device__ __forceinline__ float sigm(float x) {
    return __fdividef(1.f, 1.f + __expf(-x));
}
__device__ __forceinline__ float tanh_(float x) {
    return 1.f - __fdividef(2.f, 1.f + __expf(2.f * x));
}

// grid-wide barrier: all 128 blocks co-resident (grid must be 128)
__device__ __forceinline__ void grid_bar() {
    __threadfence();   // make this thread's prior global writes visible
    __syncthreads();
    if (threadIdx.x == 0) {
        unsigned g = g_bar_gen;
        unsigned a = atomicAdd(&g_bar_cnt, 1u);
        if (a == 127u) {
            g_bar_cnt = 0u;
            __threadfence();
            g_bar_gen = g + 1u;
        } else {
            while (g_bar_gen == g) { __nanosleep(32); }
        }
    }
    __syncthreads();
}

// ---------------- generic C = A @ W^T + b0 (+b1), tiled 64x64x16, f32x2 ----------------
// asel: 0 = Aext layer0 x mapping ([B,T,IN], row m = t*B+b)
//       1 = g_y0, 2 = g_y1, 3 = g_hT, 4 = g_z1   (row-major, lda=K)
// csel: 0 = gates (split halves, ldc=4096), 1 = g_z1 (ldc=512), 2 = g_z2 (ldc=256)
__global__ __launch_bounds__(256) void gemm_tn(
    const float* __restrict__ Aext, const float* __restrict__ W,
    const float* __restrict__ b0, const float* __restrict__ b1,
    int K, int asel, int csel)
{
    __shared__ ull   Asd[16][66];   // A duplicated pairs: [k][m] = {a,a}
    __shared__ float Bs[16][68];    // B natural: [k][n]
    const int tid = threadIdx.x;
    const int tx = tid & 15, ty = tid >> 4;
    const int m0 = blockIdx.y * 64, n0 = blockIdx.x * 64;

    const float* base = Aext;
    if (asel == 1) base = g_y0;
    else if (asel == 2) base = g_y1;
    else if (asel == 3) base = g_hT;
    else if (asel == 4) base = g_z1;

    const int r = tid >> 2, kq = tid & 3;
    const float* arow;
    if (asel == 0) {
        int mg = m0 + r;
        arow = Aext + ((size_t)(mg & 127) * 1024 + (size_t)(mg >> 7)) * 128;
    } else {
        arow = base + (size_t)(m0 + r) * K;
    }
    const float* wrow = W + (size_t)(n0 + r) * K;

    ull acc[4][2];
#pragma unroll
    for (int i = 0; i < 4; i++) { acc[i][0] = 0ull; acc[i][1] = 0ull; }

    const int nkt = K >> 4;
    float4 av = *(const float4*)(arow + kq * 4);
    float4 wv = *(const float4*)(wrow + kq * 4);

    for (int kt = 0; kt < nkt; kt++) {
        Asd[kq * 4 + 0][r] = pk(av.x, av.x);
        Asd[kq * 4 + 1][r] = pk(av.y, av.y);
        Asd[kq * 4 + 2][r] = pk(av.z, av.z);
        Asd[kq * 4 + 3][r] = pk(av.w, av.w);
        Bs[kq * 4 + 0][r] = wv.x; Bs[kq * 4 + 1][r] = wv.y;
        Bs[kq * 4 + 2][r] = wv.z; Bs[kq * 4 + 3][r] = wv.w;
        __syncthreads();
        if (kt + 1 < nkt) {
            av = *(const float4*)(arow + (kt + 1) * 16 + kq * 4);
            wv = *(const float4*)(wrow + (kt + 1) * 16 + kq * 4);
        }
#pragma unroll
        for (int k = 0; k < 16; k++) {
            ull b01 = *(const ull*)&Bs[k][tx * 4];
            ull b23 = *(const ull*)&Bs[k][tx * 4 + 2];
            ull a0 = Asd[k][ty * 4 + 0];
            ull a1 = Asd[k][ty * 4 + 1];
            ull a2 = Asd[k][ty * 4 + 2];
            ull a3 = Asd[k][ty * 4 + 3];
            acc[0][0] = f2fma(a0, b01, acc[0][0]); acc[0][1] = f2fma(a0, b23, acc[0][1]);
            acc[1][0] = f2fma(a1, b01, acc[1][0]); acc[1][1] = f2fma(a1, b23, acc[1][1]);
            acc[2][0] = f2fma(a2, b01, acc[2][0]); acc[2][1] = f2fma(a2, b23, acc[2][1]);
            acc[3][0] = f2fma(a3, b01, acc[3][0]); acc[3][1] = f2fma(a3, b23, acc[3][1]);
        }
        __syncthreads();
    }

    const int n = n0 + tx * 4;
    float bb[4];
#pragma unroll
    for (int jj = 0; jj < 4; jj++) {
        bb[jj] = b0[n + jj];
        if (b1) bb[jj] += b1[n + jj];
    }
#pragma unroll
    for (int mi = 0; mi < 4; mi++) {
        int m = m0 + ty * 4 + mi;
        float c0, c1, c2, c3;
        unpk(acc[mi][0], c0, c1);
        unpk(acc[mi][1], c2, c3);
        float4 outv = make_float4(c0 + bb[0], c1 + bb[1], c2 + bb[2], c3 + bb[3]);
        float* crow;
        if (csel == 0)      crow = (m < 65536 ? g_gatesA : g_gatesB) + (size_t)(m & 65535) * 4096;
        else if (csel == 1) crow = g_z1 + (size_t)m * 512;
        else                crow = g_z2 + (size_t)m * 256;
        *(float4*)(crow + n) = outv;
    }
}

// ---------------- persistent LSTM layer: 1024 steps in one kernel -------------
// grid = 128 blocks (j-tile of 8), 256 threads, 192KB dynamic smem.
// Thread = (j = tid&7, bg = tid>>3): 4 b x 4 gates x 1 j; acc pairs over gates.
// Dynamic smem: h dup [2][32k][128b pairs] (64KB) + Whh slice [1024k][8j][4g] (128KB).
// ysel: 0 -> write g_y0, 1 -> write g_y1, 2 -> no y, write g_hT at t==1023.
__global__ __launch_bounds__(256, 1) void lstm_layer(const float* __restrict__ Whh, int ysel)
{
    extern __shared__ float sm[];
    float* __restrict__ h_sm = sm;            // 16384 floats: [buf][k(32)][b dup(256)]
    float* __restrict__ w_sm = sm + 16384;    // 32768 floats: [k][j*4+g]

    const int tid = threadIdx.x;
    const int j = tid & 7, bg = tid >> 3;
    const int j0 = blockIdx.x << 3;
    const int jg = j0 + j;
    const int b0 = bg << 2;

    // ---- fill Whh slice once: w_sm[k][j][g] = Whh[g*1024 + jg][k] ----
    for (int idx = tid; idx < 8192; idx += 256) {
        int rg = idx >> 8, k4 = idx & 255;
        int jj = rg >> 2, g = rg & 3;
        float4 v = *(const float4*)(Whh + ((size_t)((g << 10) | (j0 + jj))) * 1024 + (k4 << 2));
        int base = (k4 << 2) * 32 + (jj << 2) + g;
        w_sm[base]      = v.x;
        w_sm[base + 32] = v.y;
        w_sm[base + 64] = v.z;
        w_sm[base + 96] = v.w;
    }
    __syncthreads();

    float cc[4] = {0.f, 0.f, 0.f, 0.f};

    // gates for t=0
    float ga[4][4];
#pragma unroll
    for (int i = 0; i < 4; i++) {
        const float* gb = g_gatesA + (size_t)(b0 + i) * 4096 + jg;
        ga[i][0] = __ldcs(gb);
        ga[i][1] = __ldcs(gb + 1024);
        ga[i][2] = __ldcs(gb + 2048);
        ga[i][3] = __ldcs(gb + 3072);
    }

    for (int t = 0; t < 1024; t++) {
        float ad[4][4]; // recurrent contribution [b_i][gate]
        if (t > 0) {
            const float* __restrict__ h_in = g_ht[t & 1];
            ull acc[4][2];
#pragma unroll
            for (int i = 0; i < 4; i++) { acc[i][0] = 0ull; acc[i][1] = 0ull; }

            float4 hp[4];
#pragma unroll
            for (int r2 = 0; r2 < 4; r2++) {
                int f = tid + 256 * r2; int kk = f >> 5, b4 = f & 31;
                hp[r2] = __ldcg((const float4*)(h_in + kk * 128 + (b4 << 2)));
            }

            for (int kt = 0; kt < 32; kt++) {
                const int bufo = (kt & 1) << 13; // *8192 floats
                // store tile, duplicated pairs
#pragma unroll
                for (int r2 = 0; r2 < 4; r2++) {
                    int f = tid + 256 * r2; int kk = f >> 5, b4 = f & 31;
                    int off = bufo + (kk << 8) + (b4 << 3);
                    *(ull*)&h_sm[off]     = pk(hp[r2].x, hp[r2].x);
                    *(ull*)&h_sm[off + 2] = pk(hp[r2].y, hp[r2].y);
                    *(ull*)&h_sm[off + 4] = pk(hp[r2].z, hp[r2].z);
                    *(ull*)&h_sm[off + 6] = pk(hp[r2].w, hp[r2].w);
                }
                __syncthreads();
                if (kt + 1 < 32) {
                    const int k0 = (kt + 1) * 32;
#pragma unroll
                    for (int r2 = 0; r2 < 4; r2++) {
                        int f = tid + 256 * r2; int kk = f >> 5, b4 = f & 31;
                        hp[r2] = __ldcg((const float4*)(h_in + (k0 + kk) * 128 + (b4 << 2)));
                    }
                }
                const float* hb = h_sm + bufo + (b0 << 1);
                const float* wb = w_sm + (kt << 10) + (j << 2);
#pragma unroll
                for (int k = 0; k < 32; k++) {
                    ull w01 = *(const ull*)&wb[k * 32];
                    ull w23 = *(const ull*)&wb[k * 32 + 2];
                    ull h0 = *(const ull*)&hb[k * 256];
                    ull h1 = *(const ull*)&hb[k * 256 + 2];
                    ull h2 = *(const ull*)&hb[k * 256 + 4];
                    ull h3 = *(const ull*)&hb[k * 256 + 6];
                    acc[0][0] = f2fma(h0, w01, acc[0][0]); acc[0][1] = f2fma(h0, w23, acc[0][1]);
                    acc[1][0] = f2fma(h1, w01, acc[1][0]); acc[1][1] = f2fma(h1, w23, acc[1][1]);
                    acc[2][0] = f2fma(h2, w01, acc[2][0]); acc[2][1] = f2fma(h2, w23, acc[2][1]);
                    acc[3][0] = f2fma(h3, w01, acc[3][0]); acc[3][1] = f2fma(h3, w23, acc[3][1]);
                }
                __syncthreads();
            }
#pragma unroll
            for (int i = 0; i < 4; i++) {
                unpk(acc[i][0], ad[i][0], ad[i][1]);
                unpk(acc[i][1], ad[i][2], ad[i][3]);
            }
        } else {
#pragma unroll
            for (int i = 0; i < 4; i++)
#pragma unroll
                for (int g = 0; g < 4; g++) ad[i][g] = 0.f;
        }

        // epilogue: activations + state update (c lives in registers)
        float hv[4];
#pragma unroll
        for (int i = 0; i < 4; i++) {
            float xi = ga[i][0] + ad[i][0];
            float xf = ga[i][1] + ad[i][1];
            float xg = ga[i][2] + ad[i][2];
            float xo = ga[i][3] + ad[i][3];
            float ii = sigm(xi), ff = sigm(xf), gg = tanh_(xg), oo = sigm(xo);
            cc[i] = ff * cc[i] + ii * gg;
            hv[i] = oo * tanh_(cc[i]);
        }
        // h(t+1) input, transposed [k=j][b]
        *(float4*)(g_ht[(t & 1) ^ 1] + (size_t)jg * 128 + b0) =
            make_float4(hv[0], hv[1], hv[2], hv[3]);
        if (ysel == 0) {
#pragma unroll
            for (int i = 0; i < 4; i++)
                g_y0[((size_t)t * 128 + b0 + i) * 1024 + jg] = hv[i];
        } else if (ysel == 1) {
#pragma unroll
            for (int i = 0; i < 4; i++)
                g_y1[((size_t)t * 128 + b0 + i) * 1024 + jg] = hv[i];
        } else if (t == 1023) {
#pragma unroll
            for (int i = 0; i < 4; i++)
                g_hT[(size_t)(b0 + i) * 1024 + jg] = hv[i];
        }

        // prefetch next step's gate pre-activations before the barrier
        float gan[4][4];
        if (t < 1023) {
            const float* gp =
                (t + 1 < 512 ? g_gatesA : g_gatesB) + (size_t)((t + 1) & 511) * (128 * 4096);
#pragma unroll
            for (int i = 0; i < 4; i++) {
                const float* gb = gp + (size_t)(b0 + i) * 4096 + jg;
                gan[i][0] = __ldcs(gb);
                gan[i][1] = __ldcs(gb + 1024);
                gan[i][2] = __ldcs(gb + 2048);
                gan[i][3] = __ldcs(gb + 3072);
            }
        }

        grid_bar();

#pragma unroll
        for (int i = 0; i < 4; i++)
#pragma unroll
            for (int g = 0; g < 4; g++) ga[i][g] = gan[i][g];
    }
}

// ---------------- BN (eval) + ReLU, in place on g_z1/g_z2 ----------------
__global__ void bn_relu(int sel, const float* __restrict__ gg, const float* __restrict__ bb,
                        const float* __restrict__ mm, const float* __restrict__ vv, int N)
{
    int idx = blockIdx.x * blockDim.x + threadIdx.x;
    if (idx < 128 * N) {
        int n = idx % N;
        float* Z = (sel == 1) ? g_z1 : g_z2;
        float x = Z[idx];
        x = (x - mm[n]) * rsqrtf(vv[n] + 1e-5f) * gg[n] + bb[n];
        Z[idx] = fmaxf(x, 0.f);
    }
}

// ---------------- final fc3 ----------------
__global__ void fc3_k(const float* __restrict__ W, const float* __restrict__ bias,
                      float* __restrict__ out)
{
    int n = blockIdx.x;     // 0..27
    int b = threadIdx.x;    // 0..127
    const float* z = g_z2 + b * 256;
    const float* w = W + n * 256;
    float acc = 0.f;
#pragma unroll 8
    for (int k = 0; k < 256; k += 4) {
        float4 zv = *(const float4*)(z + k);
        float4 wv = *(const float4*)(w + k);
        acc += zv.x * wv.x + zv.y * wv.y + zv.z * wv.z + zv.w * wv.w;
    }
    out[b * 28 + n] = acc + bias[n];
}

// ---------------- launch ----------------
extern "C" void kernel_launch(void* const* d_in, const int* in_sizes, int n_in,
                              void* d_out, int out_size)
{
    const float* x = (const float*)d_in[0];
    const float* Wih[3] = {(const float*)d_in[1], (const float*)d_in[5], (const float*)d_in[9]};
    const float* Whh[3] = {(const float*)d_in[2], (const float*)d_in[6], (const float*)d_in[10]};
    const float* bih[3] = {(const float*)d_in[3], (const float*)d_in[7], (const float*)d_in[11]};
    const float* bhh[3] = {(const float*)d_in[4], (const float*)d_in[8], (const float*)d_in[12]};
    const float* fc1_w = (const float*)d_in[13]; const float* fc1_b = (const float*)d_in[14];
    const float* bn1_g = (const float*)d_in[15]; const float* bn1_b = (const float*)d_in[16];
    const float* bn1_m = (const float*)d_in[17]; const float* bn1_v = (const float*)d_in[18];
    const float* fc2_w = (const float*)d_in[19]; const float* fc2_b = (const float*)d_in[20];
    const float* bn2_g = (const float*)d_in[21]; const float* bn2_b = (const float*)d_in[22];
    const float* bn2_m = (const float*)d_in[23]; const float* bn2_v = (const float*)d_in[24];
    const float* fc3_w = (const float*)d_in[25]; const float* fc3_b = (const float*)d_in[26];

    const int LSTM_SMEM = 49152 * sizeof(float); // 192 KB dynamic
    static int attr_done = 0;
    if (!attr_done) {
        cudaFuncSetAttribute(lstm_layer, cudaFuncAttributeMaxDynamicSharedMemorySize,
                             LSTM_SMEM);
        attr_done = 1;
    }

    for (int l = 0; l < 3; l++) {
        int K = (l == 0) ? 128 : 1024;
        int asel = (l == 0) ? 0 : ((l == 1) ? 1 : 2);
        gemm_tn<<<dim3(64, 2048), 256>>>((l == 0) ? x : nullptr, Wih[l], bih[l], bhh[l],
                                         K, asel, 0);
        int ysel = (l == 0) ? 0 : ((l == 1) ? 1 : 2);
        lstm_layer<<<128, 256, LSTM_SMEM>>>(Whh[l], ysel);
    }

    // head: final hidden of layer 2 is in g_hT
    gemm_tn<<<dim3(8, 2), 256>>>(nullptr, fc1_w, fc1_b, nullptr, 1024, 3, 1);
    bn_relu<<<256, 256>>>(1, bn1_g, bn1_b, bn1_m, bn1_v, 512);
    gemm_tn<<<dim3(4, 2), 256>>>(nullptr, fc2_w, fc2_b, nullptr, 512, 4, 2);
    bn_relu<<<128, 256>>>(2, bn2_g, bn2_b, bn2_m, bn2_v, 256);
    fc3_k<<<28, 128>>>(fc3_w, fc3_b, (float*)d_out);
}